// round 17
// baseline (speedup 1.0000x reference)
#include <cuda_runtime.h>
#include <cuda_fp16.h>
#include <cstdint>

// Problem constants
#define BATCH 4096
#define DIM   4096
#define NBLK  16
#define SEC   256

// ---------------------------------------------------------------------------
// Scratch (static device globals; no runtime allocation allowed)
// ---------------------------------------------------------------------------
__device__ __half g_h1h[(size_t)BATCH * DIM];       // 32 MB layer1 out (fp16)
__device__ float  g_w2ct[NBLK * DIM];               // compact W2
__device__ float  g_w3ct[NBLK * DIM];               // compact W3
__device__ __half g_wh[NBLK * SEC * SEC];           // 2 MB, W1 diag blocks fp16

__device__ __forceinline__ uint32_t smem_u32(const void* p) {
    uint32_t a;
    asm("{ .reg .u64 t; cvta.to.shared.u64 t, %1; cvt.u32.u64 %0, t; }"
        : "=r"(a) : "l"(p));
    return a;
}
__device__ __forceinline__ void cp_async16(uint32_t dst, const void* src) {
    asm volatile("cp.async.cg.shared.global [%0], [%1], 16;"
                 :: "r"(dst), "l"(src));
}
#define CP_COMMIT()  asm volatile("cp.async.commit_group;")
#define CP_WAIT(N)   asm volatile("cp.async.wait_group %0;" :: "n"(N))

__device__ __forceinline__ uint2 cvt4h(const float4 v)
{
    __half2 h01 = __floats2half2_rn(v.x, v.y);
    __half2 h23 = __floats2half2_rn(v.z, v.w);
    uint2 r;
    r.x = *reinterpret_cast<uint32_t*>(&h01);
    r.y = *reinterpret_cast<uint32_t*>(&h23);
    return r;
}

__device__ __forceinline__ void ldmatrix_x4(
    uint32_t& r0, uint32_t& r1, uint32_t& r2, uint32_t& r3, uint32_t addr)
{
    asm volatile("ldmatrix.sync.aligned.m8n8.x4.shared.b16 {%0,%1,%2,%3}, [%4];"
                 : "=r"(r0), "=r"(r1), "=r"(r2), "=r"(r3) : "r"(addr));
}
__device__ __forceinline__ void mma_f16(
    float* c, uint32_t a0, uint32_t a1, uint32_t a2, uint32_t a3,
    uint32_t b0, uint32_t b1)
{
    asm volatile(
        "mma.sync.aligned.m16n8k16.row.col.f32.f16.f16.f32 "
        "{%0,%1,%2,%3}, {%4,%5,%6,%7}, {%8,%9}, {%0,%1,%2,%3};"
        : "+f"(c[0]), "+f"(c[1]), "+f"(c[2]), "+f"(c[3])
        : "r"(a0), "r"(a1), "r"(a2), "r"(a3), "r"(b0), "r"(b1));
}

// ---------------------------------------------------------------------------
// Prep kernels (unchanged)
// ---------------------------------------------------------------------------
__global__ void __launch_bounds__(256) pack_kernel(const float* __restrict__ W2,
                                                   const float* __restrict__ W3)
{
    int t = blockIdx.x * 256 + threadIdx.x;
#pragma unroll
    for (int i = 0; i < 4; i++) {
        int idx = t + i * 16384;
        int k = idx >> 12;
        int o = idx & (DIM - 1);
        int c = o & (SEC - 1);
        float v2 = (k <= (o >> 8)) ? W2[o * DIM + k * SEC + c] : 0.0f;
        g_w2ct[idx] = v2;
        g_w3ct[idx] = W3[o * DIM + k * SEC + c];
    }
}

__global__ void __launch_bounds__(256) pack_w1_kernel(const float* __restrict__ W1)
{
    int idx = blockIdx.x * 256 + threadIdx.x;
    int z  = idx >> 14;
    int r  = (idx >> 6) & 255;
    int c4 = idx & 63;
    float4 v = *reinterpret_cast<const float4*>(
        &W1[(size_t)(z * SEC + r) * DIM + z * SEC + c4 * 4]);
    int o = (z * SEC + r) * SEC + c4 * 4;
    *reinterpret_cast<uint2*>(&g_wh[o]) = cvt4h(v);
}

// ---------------------------------------------------------------------------
// Layer 1 (unchanged, validated): fp16 GEMM, mma.sync, cp.async double buffer.
// ---------------------------------------------------------------------------
#define LDS       40
#define ROWB      (LDS * 2)
#define SMA       0
#define SMB       (64 * ROWB)
#define BUFSZ     (SMB + 256 * ROWB)
#define SMEM_L1   (2 * BUFSZ)

__device__ __forceinline__ void prefetch_B(
    uint32_t sbuf, int z, int k0, int tid)
{
#pragma unroll
    for (int l = 0; l < 4; l++) {
        int idx = tid + 256 * l;
        int br  = idx >> 2;
        int bp  = idx & 3;
        size_t src = (size_t)(z * SEC + br) * SEC + k0 + bp * 8;
        cp_async16(sbuf + SMB + br * ROWB + bp * 16, &g_wh[src]);
    }
}

__device__ __forceinline__ void load_A_regs(
    float4* a_pre, const float* __restrict__ X, int m0, int z, int k0, int tid)
{
    const int row   = tid >> 2;
    const int piece = tid & 3;
    const float* src = &X[(size_t)(m0 + row) * DIM + z * SEC + k0 + piece * 8];
    a_pre[0] = *reinterpret_cast<const float4*>(src);
    a_pre[1] = *reinterpret_cast<const float4*>(src + 4);
}

__global__ void __launch_bounds__(256, 2) layer1_mma_kernel(
    const float* __restrict__ X,
    const float* __restrict__ b1)
{
    extern __shared__ char dsm[];
    const uint32_t sbase = smem_u32(dsm);

    const int tid  = threadIdx.x;
    const int lane = tid & 31;
    const int wid  = tid >> 5;
    const int wm0  = (wid & 1) * 32;
    const int wn0  = (wid >> 1) * 64;
    const int m0   = blockIdx.x * 64;
    const int z    = blockIdx.y;

    const uint32_t a_sts = sbase + SMA + (tid >> 2) * ROWB + (tid & 3) * 16;

    float acc[2][8][4];
#pragma unroll
    for (int mi = 0; mi < 2; mi++)
#pragma unroll
        for (int ni = 0; ni < 8; ni++)
#pragma unroll
            for (int q = 0; q < 4; q++) acc[mi][ni][q] = 0.0f;

    const uint32_t a_off =
        ((lane & 15) * LDS + (lane >> 4) * 8) * 2;
    const uint32_t b_off =
        ((((lane >> 4) << 3) + (lane & 7)) * LDS + (((lane >> 3) & 1) << 3)) * 2;

    float4 a_pre[2];
    load_A_regs(a_pre, X, m0, z, 0, tid);
    prefetch_B(sbase, z, 0, tid);
    CP_COMMIT();

    for (int ch = 0; ch < SEC / 32; ch++) {
        const uint32_t buf = sbase + (ch & 1) * BUFSZ;

        uint4 ah;
        {
            uint2 h0 = cvt4h(a_pre[0]);
            uint2 h1 = cvt4h(a_pre[1]);
            ah.x = h0.x; ah.y = h0.y; ah.z = h1.x; ah.w = h1.y;
        }
        *reinterpret_cast<uint4*>(
            reinterpret_cast<char*>(dsm) + (buf - sbase) + (a_sts - sbase - SMA)) = ah;

        if (ch + 1 < SEC / 32) {
            load_A_regs(a_pre, X, m0, z, (ch + 1) * 32, tid);
            prefetch_B(sbase + ((ch + 1) & 1) * BUFSZ, z, (ch + 1) * 32, tid);
            CP_COMMIT();
            CP_WAIT(1);
        } else {
            CP_WAIT(0);
        }
        __syncthreads();

        const uint32_t Ab = buf + SMA;
        const uint32_t Bb = buf + SMB;

#pragma unroll
        for (int ks = 0; ks < 2; ks++) {
            uint32_t a[2][4];
#pragma unroll
            for (int mi = 0; mi < 2; mi++) {
                uint32_t addr = Ab + a_off +
                    ((wm0 + mi * 16) * LDS + ks * 16) * 2;
                ldmatrix_x4(a[mi][0], a[mi][1], a[mi][2], a[mi][3], addr);
            }
            uint32_t b[4][4];
#pragma unroll
            for (int np = 0; np < 4; np++) {
                uint32_t addr = Bb + b_off +
                    ((wn0 + np * 16) * LDS + ks * 16) * 2;
                ldmatrix_x4(b[np][0], b[np][1], b[np][2], b[np][3], addr);
            }
#pragma unroll
            for (int mi = 0; mi < 2; mi++)
#pragma unroll
                for (int ni = 0; ni < 8; ni++) {
                    int np = ni >> 1, h = (ni & 1) * 2;
                    mma_f16(acc[mi][ni],
                            a[mi][0], a[mi][1], a[mi][2], a[mi][3],
                            b[np][h], b[np][h + 1]);
                }
        }
        __syncthreads();
    }

    const int g = lane >> 2;
    const int c = lane & 3;
#pragma unroll
    for (int mi = 0; mi < 2; mi++) {
        const int row0 = m0 + wm0 + mi * 16 + g;
        const int row1 = row0 + 8;
#pragma unroll
        for (int ni = 0; ni < 8; ni++) {
            const int col = z * SEC + wn0 + ni * 8 + 2 * c;
            const float bb0 = b1[col], bb1 = b1[col + 1];
            __half2 v0 = __floats2half2_rn(
                fmaxf(acc[mi][ni][0] + bb0, 0.0f),
                fmaxf(acc[mi][ni][1] + bb1, 0.0f));
            __half2 v1 = __floats2half2_rn(
                fmaxf(acc[mi][ni][2] + bb0, 0.0f),
                fmaxf(acc[mi][ni][3] + bb1, 0.0f));
            *reinterpret_cast<__half2*>(&g_h1h[(size_t)row0 * DIM + col]) = v0;
            *reinterpret_cast<__half2*>(&g_h1h[(size_t)row1 * DIM + col]) = v1;
        }
    }
}

// ---------------------------------------------------------------------------
// FUSED layers 2+3, v4:
//  - smem operands fp32, k-pair interleaved: [r][k2][c*2 + parity] -> LDS.64
//    float2 gathers, NO cvt in inner loop.
//  - layer-2 triangle exploited: warp gq computes oy in {gq, 15-gq}
//    -> 17 FMAs instead of 32, balanced across warps; compile-time bounds
//    via switch-template dispatch (same barrier structure in all branches).
//  - layer-3 full 16 taps, outputs oy in {2gq, 2gq+1}.
// 256 threads (32 c x 8 warps), 2 CTAs/SM, FB_R=8 rows per 2 barriers.
// ---------------------------------------------------------------------------
#define FB_R    8
#define FB_BCNT 32

template<int GQ>
__device__ __forceinline__ void fused_body(
    const float* __restrict__ b2,
    const float* __restrict__ b3,
    float* __restrict__ out,
    float (&h1s)[FB_R][8][64],
    float (&h2s)[FB_R][8][64],
    int cx, int c, int ccol, int b0, int tid)
{
    constexpr int OY0 = GQ;            // layer2 output block 0 (taps k<=GQ)
    constexpr int OY1 = 15 - GQ;       // layer2 output block 1 (taps k<=15-GQ)

    // ---- weights & biases in registers
    float w2a[OY0 + 1], w2b[OY1 + 1];
#pragma unroll
    for (int k = 0; k <= OY0; k++) w2a[k] = g_w2ct[k * DIM + OY0 * SEC + ccol];
#pragma unroll
    for (int k = 0; k <= OY1; k++) w2b[k] = g_w2ct[k * DIM + OY1 * SEC + ccol];
    const float bv2a = b2[OY0 * SEC + ccol];
    const float bv2b = b2[OY1 * SEC + ccol];

    float w3[2][NBLK], bv3[2];
#pragma unroll
    for (int u = 0; u < 2; u++) {
        int o = (GQ * 2 + u) * SEC + ccol;
        bv3[u] = b3[o];
#pragma unroll
        for (int k = 0; k < NBLK; k++) w3[u][k] = g_w3ct[k * DIM + o];
    }

    // staging map: thread covers (row sr, k-pair sk2, 8 c values)
    const int sr  = tid >> 5;
    const int sk2 = (tid >> 2) & 7;
    const int sc8 = (tid & 3) * 8;

    uint4 g0, g1;
    {
        const __half* p = &g_h1h[(size_t)(b0 + sr) * DIM +
                                 (2 * sk2) * SEC + cx * 32 + sc8];
        g0 = *reinterpret_cast<const uint4*>(p);
        g1 = *reinterpret_cast<const uint4*>(p + SEC);
    }

    for (int s = 0; s < FB_BCNT; s += FB_R) {
        // ---- stage: (k even, k odd) -> interleaved fp32 pairs
        {
            const __half* e = reinterpret_cast<const __half*>(&g0);
            const __half* o = reinterpret_cast<const __half*>(&g1);
#pragma unroll
            for (int j = 0; j < 8; j++) {
                float2 f;
                f.x = __half2float(e[j]);
                f.y = __half2float(o[j]);
                *reinterpret_cast<float2*>(&h1s[sr][sk2][(sc8 + j) * 2]) = f;
            }
        }
        __syncthreads();                       // (1) h1s ready; h2s free

        // prefetch next slab (overlaps with layer-2 compute)
        if (s + FB_R < FB_BCNT) {
            const __half* p = &g_h1h[(size_t)(b0 + s + FB_R + sr) * DIM +
                                     (2 * sk2) * SEC + cx * 32 + sc8];
            g0 = *reinterpret_cast<const uint4*>(p);
            g1 = *reinterpret_cast<const uint4*>(p + SEC);
        }

        // ---- layer 2 (triangular, balanced)
#pragma unroll
        for (int r = 0; r < FB_R; r++) {
            float iv[NBLK];
#pragma unroll
            for (int k2 = 0; k2 < 8; k2++) {
                float2 t = *reinterpret_cast<const float2*>(&h1s[r][k2][c * 2]);
                iv[2 * k2]     = t.x;
                iv[2 * k2 + 1] = t.y;
            }
            float a0 = bv2a;
#pragma unroll
            for (int k = 0; k <= OY0; k++) a0 = fmaf(w2a[k], iv[k], a0);
            float a1 = bv2b;
#pragma unroll
            for (int k = 0; k <= OY1; k++) a1 = fmaf(w2b[k], iv[k], a1);
            h2s[r][OY0 >> 1][c * 2 + (OY0 & 1)] = fmaxf(a0, 0.0f);
            h2s[r][OY1 >> 1][c * 2 + (OY1 & 1)] = fmaxf(a1, 0.0f);
        }
        __syncthreads();                       // (2) h2s ready; h1s free

        // ---- layer 3 (full 16 taps)
#pragma unroll
        for (int r = 0; r < FB_R; r++) {
            float hv[NBLK];
#pragma unroll
            for (int k2 = 0; k2 < 8; k2++) {
                float2 t = *reinterpret_cast<const float2*>(&h2s[r][k2][c * 2]);
                hv[2 * k2]     = t.x;
                hv[2 * k2 + 1] = t.y;
            }
            float a0 = bv3[0], a1 = bv3[1];
#pragma unroll
            for (int k = 0; k < NBLK; k++) {
                a0 = fmaf(w3[0][k], hv[k], a0);
                a1 = fmaf(w3[1][k], hv[k], a1);
            }
            size_t ob = (size_t)(b0 + s + r) * DIM;
            out[ob + (GQ * 2 + 0) * SEC + ccol] = a0;
            out[ob + (GQ * 2 + 1) * SEC + ccol] = a1;
        }
        // no barrier: next staging writes h1s, which layer 3 never reads;
        // barrier (1) orders it before the next layer-2 reads.
    }
}

__global__ void __launch_bounds__(256, 2) fused23_kernel(
    const float* __restrict__ b2,
    const float* __restrict__ b3,
    float* __restrict__ out)
{
    const int cx   = blockIdx.x;
    const int tid  = threadIdx.x;
    const int c    = tid & 31;
    const int gq   = tid >> 5;
    const int ccol = cx * 32 + c;
    const int b0   = blockIdx.y * FB_BCNT;

    __shared__ float h1s[FB_R][8][64];        // 16 KB, k-pair interleaved
    __shared__ float h2s[FB_R][8][64];        // 16 KB

    switch (gq) {
        case 0: fused_body<0>(b2, b3, out, h1s, h2s, cx, c, ccol, b0, tid); break;
        case 1: fused_body<1>(b2, b3, out, h1s, h2s, cx, c, ccol, b0, tid); break;
        case 2: fused_body<2>(b2, b3, out, h1s, h2s, cx, c, ccol, b0, tid); break;
        case 3: fused_body<3>(b2, b3, out, h1s, h2s, cx, c, ccol, b0, tid); break;
        case 4: fused_body<4>(b2, b3, out, h1s, h2s, cx, c, ccol, b0, tid); break;
        case 5: fused_body<5>(b2, b3, out, h1s, h2s, cx, c, ccol, b0, tid); break;
        case 6: fused_body<6>(b2, b3, out, h1s, h2s, cx, c, ccol, b0, tid); break;
        default: fused_body<7>(b2, b3, out, h1s, h2s, cx, c, ccol, b0, tid); break;
    }
}

// ---------------------------------------------------------------------------
// Launch. Inputs (metadata order): x, W1, b1, W2, b2, W3, b3, m1, m2, m3
// ---------------------------------------------------------------------------
extern "C" void kernel_launch(void* const* d_in, const int* in_sizes, int n_in,
                              void* d_out, int out_size)
{
    const float* x  = (const float*)d_in[0];
    const float* W1 = (const float*)d_in[1];
    const float* b1 = (const float*)d_in[2];
    const float* W2 = (const float*)d_in[3];
    const float* b2 = (const float*)d_in[4];
    const float* W3 = (const float*)d_in[5];
    const float* b3 = (const float*)d_in[6];
    float* out = (float*)d_out;
    (void)in_sizes; (void)n_in; (void)out_size;

    static bool attr_set = false;
    if (!attr_set) {
        cudaFuncSetAttribute(layer1_mma_kernel,
                             cudaFuncAttributeMaxDynamicSharedMemorySize,
                             SMEM_L1);
        attr_set = true;
    }

    // 1) Prep: sparse tables + fp16 weight pack
    pack_kernel<<<64, 256>>>(W2, W3);
    pack_w1_kernel<<<(NBLK * SEC * 64) / 256, 256>>>(W1);

    // 2) Layer 1: fp16 GEMM (unchanged)
    layer1_mma_kernel<<<dim3(BATCH / 64, NBLK), 256, SMEM_L1>>>(x, b1);

    // 3) Layers 2+3 fused, v4 (fp32 LDS.64 operands, triangular layer 2)
    fused23_kernel<<<dim3(8, BATCH / FB_BCNT), 256>>>(b2, b3, out);
}